// round 1
// baseline (speedup 1.0000x reference)
#include <cuda_runtime.h>
#include <math.h>

// Problem constants
#define Bb 256
#define Dd 2048
#define Nn 65536
#define Pp 4096
#define CTOT (Pp + Nn)
#define TEMP_INV 20.0f     // 1 / 0.05
#define EPS_ 0.1f

// GEMM tiling
#define BM 64
#define BN 64
#define BK 16

// Scratch (device globals — no allocation allowed)
__device__ float g_xn[Bb * Dd];                 // normalized inputs, 2 MB
__device__ float g_logits[(size_t)Bb * Nn];     // raw dot products, 64 MB
__device__ float g_rowloss[Bb];

// ---------------------------------------------------------------------------
// K1: row-normalize inputs into g_xn. One block per row.
// ---------------------------------------------------------------------------
__global__ void k_normalize(const float* __restrict__ in) {
    int row = blockIdx.x;
    const float* src = in + (size_t)row * Dd;
    float ss = 0.f;
    for (int i = threadIdx.x; i < Dd; i += 256) {
        float v = src[i];
        ss += v * v;
    }
    // warp reduce
    #pragma unroll
    for (int o = 16; o; o >>= 1) ss += __shfl_xor_sync(0xffffffffu, ss, o);
    __shared__ float sh[8];
    int lane = threadIdx.x & 31, w = threadIdx.x >> 5;
    if (lane == 0) sh[w] = ss;
    __syncthreads();
    if (threadIdx.x == 0) {
        float tot = 0.f;
        #pragma unroll
        for (int i = 0; i < 8; i++) tot += sh[i];
        sh[0] = rsqrtf(tot);
    }
    __syncthreads();
    float inv = sh[0];
    float* dst = g_xn + (size_t)row * Dd;
    for (int i = threadIdx.x; i < Dd; i += 256) dst[i] = src[i] * inv;
}

// ---------------------------------------------------------------------------
// K2: SGEMM  g_logits[b][n] = sum_k g_xn[b][k] * F[n][k]
// 64x64 tile, BK=16, 256 threads, 4x4 per-thread microtile.
// ---------------------------------------------------------------------------
__global__ void __launch_bounds__(256) k_gemm(const float* __restrict__ F) {
    __shared__ float Xs[BK][BM + 1];
    __shared__ float Fs[BK][BN + 1];

    int tid = threadIdx.x;
    int tx = tid & 15;        // 0..15
    int ty = tid >> 4;        // 0..15
    int m0 = blockIdx.y * BM;
    int n0 = blockIdx.x * BN;

    int lrow = tid >> 2;           // 0..63
    int lcol = (tid & 3) << 2;     // 0,4,8,12

    float acc[4][4] = {};

    const float* Xg = g_xn + (size_t)(m0 + lrow) * Dd + lcol;
    const float* Fg = F + (size_t)(n0 + lrow) * Dd + lcol;

    for (int k0 = 0; k0 < Dd; k0 += BK) {
        float4 xv = *(const float4*)(Xg + k0);
        float4 fv = *(const float4*)(Fg + k0);
        Xs[lcol + 0][lrow] = xv.x;
        Xs[lcol + 1][lrow] = xv.y;
        Xs[lcol + 2][lrow] = xv.z;
        Xs[lcol + 3][lrow] = xv.w;
        Fs[lcol + 0][lrow] = fv.x;
        Fs[lcol + 1][lrow] = fv.y;
        Fs[lcol + 2][lrow] = fv.z;
        Fs[lcol + 3][lrow] = fv.w;
        __syncthreads();

        #pragma unroll
        for (int kk = 0; kk < BK; kk++) {
            float xr[4], fr[4];
            #pragma unroll
            for (int i = 0; i < 4; i++) xr[i] = Xs[kk][ty * 4 + i];
            #pragma unroll
            for (int j = 0; j < 4; j++) fr[j] = Fs[kk][tx * 4 + j];
            #pragma unroll
            for (int i = 0; i < 4; i++)
                #pragma unroll
                for (int j = 0; j < 4; j++)
                    acc[i][j] += xr[i] * fr[j];
        }
        __syncthreads();
    }

    #pragma unroll
    for (int i = 0; i < 4; i++) {
        float4 v = make_float4(acc[i][0], acc[i][1], acc[i][2], acc[i][3]);
        *(float4*)(g_logits + (size_t)(m0 + ty * 4 + i) * Nn + n0 + tx * 4) = v;
    }
}

// ---------------------------------------------------------------------------
// K3: per-row online logsumexp + sum(z) + z_target. One block per batch row.
// ---------------------------------------------------------------------------
__global__ void k_rowreduce(const float* __restrict__ proto,
                            const int* __restrict__ targets) {
    int b = blockIdx.x;
    int tid = threadIdx.x;

    float m = -1e30f;
    float s = 0.f;
    float t = 0.f;

    const float* pr = proto + (size_t)b * Pp;
    for (int j = tid; j < Pp; j += 256) {
        float z = pr[j] * TEMP_INV;
        t += z;
        if (z > m) { s *= __expf(m - z); m = z; }
        s += __expf(z - m);
    }
    const float* lg = g_logits + (size_t)b * Nn;
    for (int j = tid; j < Nn; j += 256) {
        float z = lg[j] * TEMP_INV;
        t += z;
        if (z > m) { s *= __expf(m - z); m = z; }
        s += __expf(z - m);
    }

    __shared__ float ms[256], ss[256], ts[256];
    ms[tid] = m; ss[tid] = s; ts[tid] = t;
    __syncthreads();
    for (int o = 128; o; o >>= 1) {
        if (tid < o) {
            float m2 = ms[tid + o], s2 = ss[tid + o];
            float m1 = ms[tid],     s1 = ss[tid];
            float mm = fmaxf(m1, m2);
            ss[tid] = s1 * __expf(m1 - mm) + s2 * __expf(m2 - mm);
            ms[tid] = mm;
            ts[tid] += ts[tid + o];
        }
        __syncthreads();
    }
    if (tid == 0) {
        float lse = ms[0] + logf(ss[0]);
        float zt = lg[targets[b]] * TEMP_INV;
        float meanz = ts[0] / (float)CTOT;
        g_rowloss[b] = lse - (1.f - EPS_) * zt - EPS_ * meanz;
    }
}

// ---------------------------------------------------------------------------
// K4: deterministic final mean over 256 row losses.
// ---------------------------------------------------------------------------
__global__ void k_final(float* __restrict__ out) {
    int tid = threadIdx.x;
    float v = g_rowloss[tid];
    #pragma unroll
    for (int o = 16; o; o >>= 1) v += __shfl_xor_sync(0xffffffffu, v, o);
    __shared__ float sh[8];
    if ((tid & 31) == 0) sh[tid >> 5] = v;
    __syncthreads();
    if (tid == 0) {
        float s = 0.f;
        #pragma unroll
        for (int i = 0; i < 8; i++) s += sh[i];
        out[0] = s / (float)Bb;
    }
}

// ---------------------------------------------------------------------------
extern "C" void kernel_launch(void* const* d_in, const int* in_sizes, int n_in,
                              void* d_out, int out_size) {
    const float* inputs    = (const float*)d_in[0];   // [256, 2048] f32
    const int*   targets   = (const int*)  d_in[1];   // [256] i32
    const float* prototype = (const float*)d_in[2];   // [256, 4096] f32
    const float* features  = (const float*)d_in[3];   // [65536, 2048] f32
    float* out = (float*)d_out;

    k_normalize<<<Bb, 256>>>(inputs);

    dim3 g2(Nn / BN, Bb / BM);
    k_gemm<<<g2, 256>>>(features);

    k_rowreduce<<<Bb, 256>>>(prototype, targets);

    k_final<<<1, 256>>>(out);
}

// round 3
// speedup vs baseline: 7.6330x; 7.6330x over previous
#include <cuda_runtime.h>
#include <cuda_bf16.h>
#include <math.h>
#include <stdint.h>

#define Bb 256
#define Dd 2048
#define Nn 65536
#define Pp 4096
#define CTOT (Pp + Nn)
#define TEMP_INV 20.0f
#define EPS_ 0.1f

// GEMM tiling
#define BM 256
#define BN 128
#define BK 32
#define SSTR 40            // smem row stride in bf16 (32 + 8 pad)

#define ABUF (BM * SSTR)   // elems per A buffer (10240)
#define BBUF (BN * SSTR)   // elems per B buffer (5120)
#define NIT  (Dd / BK)     // 64 k-iterations

__device__ __nv_bfloat16 g_xnb[Bb * Dd];        // normalized inputs in bf16 (1 MB)
__device__ float g_logits[(size_t)Bb * Nn];     // raw dot products (64 MB)
__device__ float g_rowloss[Bb];

// ---------------------------------------------------------------------------
// K1: row-normalize inputs into bf16. One block (256 thr) per row.
// ---------------------------------------------------------------------------
__global__ void k_normalize(const float* __restrict__ in) {
    int row = blockIdx.x;
    int tid = threadIdx.x;
    const float4* src = (const float4*)(in + (size_t)row * Dd);
    float4 v0 = src[tid];
    float4 v1 = src[tid + 256];
    float ss = v0.x*v0.x + v0.y*v0.y + v0.z*v0.z + v0.w*v0.w
             + v1.x*v1.x + v1.y*v1.y + v1.z*v1.z + v1.w*v1.w;
    #pragma unroll
    for (int o = 16; o; o >>= 1) ss += __shfl_xor_sync(0xffffffffu, ss, o);
    __shared__ float sh[8];
    if ((tid & 31) == 0) sh[tid >> 5] = ss;
    __syncthreads();
    if (tid == 0) {
        float tot = 0.f;
        #pragma unroll
        for (int i = 0; i < 8; i++) tot += sh[i];
        sh[0] = rsqrtf(tot);
    }
    __syncthreads();
    float inv = sh[0];
    __nv_bfloat16* dst = g_xnb + (size_t)row * Dd;
    __nv_bfloat162 p;
    p = __floats2bfloat162_rn(v0.x*inv, v0.y*inv); *(__nv_bfloat162*)(dst + tid*4)           = p;
    p = __floats2bfloat162_rn(v0.z*inv, v0.w*inv); *(__nv_bfloat162*)(dst + tid*4 + 2)       = p;
    p = __floats2bfloat162_rn(v1.x*inv, v1.y*inv); *(__nv_bfloat162*)(dst + (tid+256)*4)     = p;
    p = __floats2bfloat162_rn(v1.z*inv, v1.w*inv); *(__nv_bfloat162*)(dst + (tid+256)*4 + 2) = p;
}

// ---------------------------------------------------------------------------
// Helpers for K2
// ---------------------------------------------------------------------------
__device__ __forceinline__ void ldsm4(uint32_t& r0, uint32_t& r1, uint32_t& r2,
                                      uint32_t& r3, uint32_t addr) {
    asm volatile(
        "ldmatrix.sync.aligned.m8n8.x4.shared.b16 {%0,%1,%2,%3}, [%4];"
        : "=r"(r0), "=r"(r1), "=r"(r2), "=r"(r3) : "r"(addr));
}

__device__ __forceinline__ void mma_bf16(float c[4], const uint32_t a[4],
                                         uint32_t b0, uint32_t b1) {
    asm volatile(
        "mma.sync.aligned.m16n8k16.row.col.f32.bf16.bf16.f32 "
        "{%0,%1,%2,%3},{%4,%5,%6,%7},{%8,%9},{%0,%1,%2,%3};"
        : "+f"(c[0]), "+f"(c[1]), "+f"(c[2]), "+f"(c[3])
        : "r"(a[0]), "r"(a[1]), "r"(a[2]), "r"(a[3]), "r"(b0), "r"(b1));
}

__device__ __forceinline__ void cvt_sts8(__nv_bfloat16* dst, float4 v) {
    __nv_bfloat162 l = __floats2bfloat162_rn(v.x, v.y);
    __nv_bfloat162 h = __floats2bfloat162_rn(v.z, v.w);
    uint2 u;
    u.x = *(uint32_t*)&l;
    u.y = *(uint32_t*)&h;
    *(uint2*)dst = u;
}

__device__ __forceinline__ void compute_tile(const uint32_t aAddr[4],
                                             const uint32_t bAddr[2],
                                             uint32_t offA, uint32_t offB,
                                             float c[4][4][4]) {
    #pragma unroll
    for (int ks = 0; ks < 2; ks++) {
        uint32_t A_[4][4], B_[2][4];
        #pragma unroll
        for (int mt = 0; mt < 4; mt++)
            ldsm4(A_[mt][0], A_[mt][1], A_[mt][2], A_[mt][3],
                  aAddr[mt] + offA + ks * 32);
        #pragma unroll
        for (int u = 0; u < 2; u++)
            ldsm4(B_[u][0], B_[u][1], B_[u][2], B_[u][3],
                  bAddr[u] + offB + ks * 32);
        #pragma unroll
        for (int mt = 0; mt < 4; mt++) {
            mma_bf16(c[mt][0], A_[mt], B_[0][0], B_[0][1]);
            mma_bf16(c[mt][1], A_[mt], B_[0][2], B_[0][3]);
            mma_bf16(c[mt][2], A_[mt], B_[1][0], B_[1][1]);
            mma_bf16(c[mt][3], A_[mt], B_[1][2], B_[1][3]);
        }
    }
}

// ---------------------------------------------------------------------------
// K2: bf16 tensor-core GEMM  g_logits[m][n] = sum_k xnb[m][k] * F[n][k]
// 256x128 block tile, BK=32, 512 threads (16 warps, 4x4), warp tile 64x32.
// F converted fp32->bf16 in flight. Double-buffered smem.
// ---------------------------------------------------------------------------
__global__ void __launch_bounds__(512, 1) k_gemm(const float* __restrict__ F) {
    extern __shared__ __nv_bfloat16 sm[];
    // layout: A buf0 [0,ABUF), A buf1 [ABUF,2*ABUF), B buf0 [2*ABUF, +BBUF), B buf1
    int tid = threadIdx.x, lane = tid & 31, wid = tid >> 5;
    int wm = wid >> 2, wn = wid & 3;
    int n0 = blockIdx.x * BN;

    // --- global load assignments ---
    int ar = tid >> 2;            // 0..127 (rows; +128 second chunk)
    int ac = (tid & 3) << 3;      // bf16 col 0,8,16,24
    const uint4* gA0 = (const uint4*)(g_xnb + (size_t)ar * Dd + ac);
    const uint4* gA1 = (const uint4*)(g_xnb + (size_t)(ar + 128) * Dd + ac);
    int fr = tid >> 3;            // 0..63 (rows; +64 second chunk)
    int fc = (tid & 7) << 2;      // float col 0,4,...,28
    const float4* gF0 = (const float4*)(F + (size_t)(n0 + fr) * Dd + fc);
    const float4* gF1 = (const float4*)(F + (size_t)(n0 + fr + 64) * Dd + fc);

    int stsA0 = ar * SSTR + ac;
    int stsA1 = (ar + 128) * SSTR + ac;
    int stsF0 = 2 * ABUF + fr * SSTR + fc;
    int stsF1 = 2 * ABUF + (fr + 64) * SSTR + fc;

    // --- ldmatrix lane addresses (bytes, buffer 0) ---
    uint32_t smbase = (uint32_t)__cvta_generic_to_shared(sm);
    uint32_t aAddr[4], bAddr[2];
    {
        int r8 = lane & 7, j = lane >> 3;
        #pragma unroll
        for (int mt = 0; mt < 4; mt++) {
            int row = wm * 64 + mt * 16 + r8 + (j & 1) * 8;
            int col = (j >> 1) * 8;
            aAddr[mt] = smbase + (uint32_t)(row * SSTR + col) * 2u;
        }
        #pragma unroll
        for (int u = 0; u < 2; u++) {
            int row = wn * 32 + u * 16 + r8 + (j >> 1) * 8;
            int col = (j & 1) * 8;
            bAddr[u] = smbase + (uint32_t)(2 * ABUF + row * SSTR + col) * 2u;
        }
    }

    float c[4][4][4];
    #pragma unroll
    for (int i = 0; i < 4; i++)
        #pragma unroll
        for (int j = 0; j < 4; j++)
            #pragma unroll
            for (int k = 0; k < 4; k++) c[i][j][k] = 0.f;

    uint4 ra0, ra1;
    float4 rf0, rf1;

    // prologue: load + store tile 0
    ra0 = gA0[0]; ra1 = gA1[0]; rf0 = gF0[0]; rf1 = gF1[0];
    *(uint4*)(sm + stsA0) = ra0;
    *(uint4*)(sm + stsA1) = ra1;
    cvt_sts8(sm + stsF0, rf0);
    cvt_sts8(sm + stsF1, rf1);
    __syncthreads();

    for (int it = 0; it < NIT - 1; it++) {
        int buf = it & 1;
        // prefetch next tile from global
        ra0 = gA0[(it + 1) * 4];
        ra1 = gA1[(it + 1) * 4];
        rf0 = gF0[(it + 1) * 8];
        rf1 = gF1[(it + 1) * 8];

        compute_tile(aAddr, bAddr,
                     (uint32_t)buf * (ABUF * 2u), (uint32_t)buf * (BBUF * 2u), c);

        int nb = buf ^ 1;
        *(uint4*)(sm + nb * ABUF + stsA0) = ra0;
        *(uint4*)(sm + nb * ABUF + stsA1) = ra1;
        cvt_sts8(sm + nb * BBUF + stsF0, rf0);
        cvt_sts8(sm + nb * BBUF + stsF1, rf1);
        __syncthreads();
    }
    compute_tile(aAddr, bAddr,
                 (uint32_t)((NIT - 1) & 1) * (ABUF * 2u),
                 (uint32_t)((NIT - 1) & 1) * (BBUF * 2u), c);

    // epilogue: write fp32 logits
    int orow = wm * 64 + (lane >> 2);
    int ocol = n0 + wn * 32 + (lane & 3) * 2;
    #pragma unroll
    for (int mt = 0; mt < 4; mt++) {
        #pragma unroll
        for (int j = 0; j < 4; j++) {
            size_t base = (size_t)(orow + mt * 16) * Nn + ocol + j * 8;
            *(float2*)&g_logits[base] = make_float2(c[mt][j][0], c[mt][j][1]);
            *(float2*)&g_logits[base + 8 * (size_t)Nn] =
                make_float2(c[mt][j][2], c[mt][j][3]);
        }
    }
}

// ---------------------------------------------------------------------------
// K3: per-row loss. Pass 1: max + sum(z). Pass 2: thresholded sum-exp
// (warps whose max z < M-30 skip all MUFU work; error < 1e-9 relative).
// ---------------------------------------------------------------------------
__global__ void k_rowreduce(const float* __restrict__ proto,
                            const int* __restrict__ targets) {
    int b = blockIdx.x, tid = threadIdx.x;
    const float4* pr = (const float4*)(proto + (size_t)b * Pp);
    const float4* lg = (const float4*)(g_logits + (size_t)b * Nn);

    float m = -1e30f, t = 0.f;
    #pragma unroll 4
    for (int i = tid; i < Pp / 4; i += 256) {
        float4 v = pr[i];
        t += ((v.x + v.y) + (v.z + v.w)) * TEMP_INV;
        m = fmaxf(m, fmaxf(fmaxf(v.x, v.y), fmaxf(v.z, v.w)));
    }
    #pragma unroll 4
    for (int i = tid; i < Nn / 4; i += 256) {
        float4 v = lg[i];
        t += ((v.x + v.y) + (v.z + v.w)) * TEMP_INV;
        m = fmaxf(m, fmaxf(fmaxf(v.x, v.y), fmaxf(v.z, v.w)));
    }
    m *= TEMP_INV;

    __shared__ float rm[256], rs[256];
    rm[tid] = m; rs[tid] = t;
    __syncthreads();
    for (int o = 128; o; o >>= 1) {
        if (tid < o) {
            rm[tid] = fmaxf(rm[tid], rm[tid + o]);
            rs[tid] += rs[tid + o];
        }
        __syncthreads();
    }
    float M = rm[0], T = rs[0];
    __syncthreads();

    float thresh = (M - 30.f) * (1.0f / TEMP_INV);   // compare against raw values
    float s = 0.f;
    for (int i = tid; i < Pp / 4; i += 256) {
        float4 v = pr[i];
        float mx = fmaxf(fmaxf(v.x, v.y), fmaxf(v.z, v.w));
        if (__any_sync(0xffffffffu, mx > thresh)) {
            s += __expf(v.x * TEMP_INV - M) + __expf(v.y * TEMP_INV - M)
               + __expf(v.z * TEMP_INV - M) + __expf(v.w * TEMP_INV - M);
        }
    }
    for (int i = tid; i < Nn / 4; i += 256) {
        float4 v = lg[i];
        float mx = fmaxf(fmaxf(v.x, v.y), fmaxf(v.z, v.w));
        if (__any_sync(0xffffffffu, mx > thresh)) {
            s += __expf(v.x * TEMP_INV - M) + __expf(v.y * TEMP_INV - M)
               + __expf(v.z * TEMP_INV - M) + __expf(v.w * TEMP_INV - M);
        }
    }
    rs[tid] = s;
    __syncthreads();
    for (int o = 128; o; o >>= 1) {
        if (tid < o) rs[tid] += rs[tid + o];
        __syncthreads();
    }
    if (tid == 0) {
        float lse = M + logf(rs[0]);
        float zt = g_logits[(size_t)b * Nn + targets[b]] * TEMP_INV;
        g_rowloss[b] = lse - (1.f - EPS_) * zt - EPS_ * (T / (float)CTOT);
    }
}

// ---------------------------------------------------------------------------
// K4: deterministic final mean over 256 row losses.
// ---------------------------------------------------------------------------
__global__ void k_final(float* __restrict__ out) {
    int tid = threadIdx.x;
    float v = g_rowloss[tid];
    #pragma unroll
    for (int o = 16; o; o >>= 1) v += __shfl_xor_sync(0xffffffffu, v, o);
    __shared__ float sh[8];
    if ((tid & 31) == 0) sh[tid >> 5] = v;
    __syncthreads();
    if (tid == 0) {
        float s = 0.f;
        #pragma unroll
        for (int i = 0; i < 8; i++) s += sh[i];
        out[0] = s / (float)Bb;
    }
}

// ---------------------------------------------------------------------------
extern "C" void kernel_launch(void* const* d_in, const int* in_sizes, int n_in,
                              void* d_out, int out_size) {
    const float* inputs    = (const float*)d_in[0];   // [256, 2048] f32
    const int*   targets   = (const int*)  d_in[1];   // [256] i32
    const float* prototype = (const float*)d_in[2];   // [256, 4096] f32
    const float* features  = (const float*)d_in[3];   // [65536, 2048] f32
    float* out = (float*)d_out;

    const int smem_bytes = (2 * ABUF + 2 * BBUF) * 2;   // 61440
    static int configured = 0;
    if (!configured) {
        cudaFuncSetAttribute(k_gemm, cudaFuncAttributeMaxDynamicSharedMemorySize,
                             smem_bytes);
        configured = 1;
    }

    k_normalize<<<Bb, 256>>>(inputs);
    k_gemm<<<Nn / BN, 512, smem_bytes>>>(features);
    k_rowreduce<<<Bb, 256>>>(prototype, targets);
    k_final<<<1, 256>>>(out);
}